// round 6
// baseline (speedup 1.0000x reference)
#include <cuda_runtime.h>
#include <math.h>

#define NBLK 128
#define NTHR 512

#define Bn 64
#define Hn 512
#define Sn 512
#define BH (Bn*Hn)         // 32768

typedef unsigned long long ull;

// output section offsets (floats)
#define O_HID   0ull
#define O_HMU   16777216ull
#define O_HSTD  33587200ull
#define O_CMU   50397184ull
#define O_CSTD  67207168ull
#define O_HT    84017152ull
#define O_CT    84049920ull

// persistent state, [n][b] layout (b contiguous)
__device__ float g_h[BH], g_c[BH], g_hn[BH], g_cn[BH];
__device__ float g_xT[(size_t)Sn * 512 * 64];   // [s][k][b]
__device__ unsigned g_cnt = 0;
__device__ volatile unsigned g_gen = 0;

__device__ __forceinline__ void grid_bar() {
    __syncthreads();
    if (threadIdx.x == 0) {
        __threadfence();
        unsigned gen = g_gen;
        if (atomicAdd(&g_cnt, 1u) == NBLK - 1) {
            g_cnt = 0;
            __threadfence();
            g_gen = gen + 1;
        } else {
            while (g_gen == gen) { }
            __threadfence();
        }
    }
    __syncthreads();
}

__device__ __forceinline__ float sigm(float v) { return 1.0f / (1.0f + expf(-v)); }
__device__ __forceinline__ float softplus(float v) {
    return fmaxf(v, 0.0f) + log1pf(expf(-fabsf(v)));
}

__device__ __forceinline__ ull pack2(float a, float b) {
    ull r; asm("mov.b64 %0, {%1, %2};" : "=l"(r) : "f"(a), "f"(b)); return r;
}
__device__ __forceinline__ ull fma2(ull a, ull b, ull c) {
    ull d; asm("fma.rn.f32x2 %0, %1, %2, %3;" : "=l"(d) : "l"(a), "l"(b), "l"(c)); return d;
}
__device__ __forceinline__ ull add2(ull a, ull b) {
    ull d; asm("add.rn.f32x2 %0, %1, %2;" : "=l"(d) : "l"(a), "l"(b)); return d;
}

// one-time x transpose: x[b][s][k] -> g_xT[s][k][b]
__global__ void xT_kernel(const float* __restrict__ x) {
    __shared__ float t[32][33];
    int s = blockIdx.x, k0 = blockIdx.y << 5, b0 = blockIdx.z << 5;
    int tx = threadIdx.x, ty = threadIdx.y;
    for (int bb = ty; bb < 32; bb += 8)
        t[bb][tx] = x[((size_t)(b0 + bb) * Sn + s) * 512 + k0 + tx];
    __syncthreads();
    for (int kk = ty; kk < 32; kk += 8)
        g_xT[((size_t)s * 512 + k0 + kk) * 64 + b0 + tx] = t[tx][kk];
}

// SMEM (floats): sW1 16384 | sW2 8192 | region: Aw(2x4096) aliased with red(16x1152)
#define SM_W2 16384
#define SM_RG 24576
#define SMEM_FLOATS (24576 + 18432)
#define SMEM_BYTES (SMEM_FLOATS * 4)

__global__ __launch_bounds__(NTHR, 1)
void rglstm(const float* __restrict__ W_ih, const float* __restrict__ W_hh,
            const float* __restrict__ b_ih, const float* __restrict__ b_hh,
            const float* __restrict__ W_hg, const float* __restrict__ W_cg,
            const float* __restrict__ eps_h, const float* __restrict__ eps_c,
            float* __restrict__ out)
{
    extern __shared__ float smem[];
    float* sW1 = smem;
    float* sW2 = smem + SM_W2;
    float* Aw  = smem + SM_RG;   // 2 x [64][64]
    float* red = smem + SM_RG;   // [16][16*72]  (alias, disjoint in time)

    const int tid = threadIdx.x;
    const int cb  = blockIdx.x;
    const bool isH = cb < 64;
    const int n0_1 = cb << 2;            // stage1: 4 hidden cols x 4 gates
    const int n0_2 = (cb & 63) << 3;     // stage2: 8 hidden cols (mu+std)

    // compute geometry: 32 k-groups x 16 tile-threads; tile 8r x 8c
    const int g  = tid >> 4;
    const int tt = tid & 15;
    const int r0 = (tt >> 1) << 3;       // 0,8,...,56
    const int c0 = (tt & 1) << 3;        // 0 or 8
    const int lane = tid & 31;
    const int p  = tid >> 5;             // partial slot = warp id (0..15)
    const int cjbase = (lane >= 16) ? 4 : 0;

    // ---- persistent weight slices into SMEM ----
    for (int i = tid; i < 16 * 1024; i += NTHR) {
        int c = i >> 10, k = i & 1023;
        int gcol = ((c >> 2) << 9) + n0_1 + (c & 3);
        sW1[k * 16 + c] = (k < 512) ? W_ih[gcol * 512 + k] : W_hh[gcol * 512 + (k - 512)];
    }
    const float* Wg = isH ? W_hg : W_cg;
    for (int i = tid; i < 16 * 512; i += NTHR) {
        int k = i >> 4, c = i & 15;
        int pcol = (c < 8) ? (n0_2 + c) : (512 + n0_2 + (c - 8));
        sW2[k * 16 + c] = Wg[k * 1024 + pcol];
    }

    // epilogue-1 geometry + biases (threads 0..255)
    const int e_b  = tid & 63;
    const int e_nn = (tid >> 6) & 3;
    float bias[4];
    #pragma unroll
    for (int gg = 0; gg < 4; ++gg) {
        int gcol = (gg << 9) + n0_1 + e_nn;
        bias[gg] = b_ih[gcol] + b_hh[gcol];
    }
    // epilogue-2 geometry
    const int e2_nn = tid & 7;
    const int e2_b  = tid >> 3;          // 0..63

    // ---- t=0 init ----
    if (tid < 256) {
        const float LN2 = 0.693147180559945309f;
        int i = cb * 256 + tid;          // 0..32767 = n*64+b
        int b = i & 63, n = i >> 6;
        g_h[i] = fmaf(eps_h[(size_t)b * 512 + n], LN2, 1e-6f);
        g_c[i] = fmaf(eps_c[(size_t)b * 512 + n], LN2, 1e-6f);
        size_t o = (size_t)b * 262656 + n;
        out[O_HMU  + o] = 1e-6f;
        out[O_HSTD + o] = LN2;
        out[O_CMU  + o] = 1e-6f;
        out[O_CSTD + o] = LN2;
    }
    grid_bar();

    const float* Asrc2  = isH ? g_hn  : g_cn;
    float*       Sdst   = isH ? g_h   : g_c;
    const float* epsP   = isH ? eps_h : eps_c;
    const size_t muB = isH ? O_HMU  : O_CMU;
    const size_t sdB = isH ? O_HSTD : O_CSTD;
    const size_t tB  = isH ? O_HT   : O_CT;

    for (int s = 0; s < Sn; ++s) {
        ull acc[32];

        // ================= stage 1: 16 windows of 64 k (w<8: x, w>=8: h) ======
        #pragma unroll
        for (int i = 0; i < 32; ++i) acc[i] = 0ull;
        const float* xbase = g_xT + (size_t)s * 32768;

        float4 pre0, pre1;
        {   // prologue: window 0 -> buf0; window 1 -> regs
            const float4* src = (const float4*)xbase;
            pre0 = __ldcg(src + tid); pre1 = __ldcg(src + tid + 512);
            float4* dst = (float4*)Aw;
            dst[tid] = pre0; dst[tid + 512] = pre1;
            src = (const float4*)(xbase + 4096);
            pre0 = __ldcg(src + tid); pre1 = __ldcg(src + tid + 512);
        }
        __syncthreads();
        for (int w = 0; w < 16; ++w) {
            if (w + 1 < 16) {
                float4* dst = (float4*)(Aw + ((w + 1) & 1) * 4096);
                dst[tid] = pre0; dst[tid + 512] = pre1;
            }
            if (w + 2 < 16) {
                const float4* src = (w + 2 < 8)
                    ? (const float4*)(xbase + (size_t)(w + 2) * 4096)
                    : (const float4*)(g_h + (w + 2 - 8) * 4096);
                pre0 = __ldcg(src + tid); pre1 = __ldcg(src + tid + 512);
            }
            const float* Ab = Aw + (w & 1) * 4096;
            #pragma unroll
            for (int j = 0; j < 2; ++j) {
                int kl = j * 32 + g;
                const float* ar = Ab + kl * 64 + r0;
                ulonglong2 aA = *(const ulonglong2*)ar;
                ulonglong2 aB = *(const ulonglong2*)(ar + 4);
                const float* wr = sW1 + (w * 64 + kl) * 16 + c0;
                float4 w0v = *(const float4*)wr;
                float4 w1v = *(const float4*)(wr + 4);
                float wc[8] = {w0v.x, w0v.y, w0v.z, w0v.w, w1v.x, w1v.y, w1v.z, w1v.w};
                #pragma unroll
                for (int cj = 0; cj < 8; ++cj) {
                    ull wp = pack2(wc[cj], wc[cj]);
                    acc[cj * 4 + 0] = fma2(aA.x, wp, acc[cj * 4 + 0]);
                    acc[cj * 4 + 1] = fma2(aA.y, wp, acc[cj * 4 + 1]);
                    acc[cj * 4 + 2] = fma2(aB.x, wp, acc[cj * 4 + 2]);
                    acc[cj * 4 + 3] = fma2(aB.y, wp, acc[cj * 4 + 3]);
                }
            }
            __syncthreads();
        }
        // fold paired k-groups, write 16 partials
        #pragma unroll
        for (int i = 0; i < 32; ++i) {
            ull o = __shfl_xor_sync(0xffffffffu, acc[i], 16);
            acc[i] = add2(acc[i], o);
        }
        {
            float* rp_ = red + p * 1152;
            #pragma unroll
            for (int cj = 0; cj < 4; ++cj) {
                int c = c0 + cjbase + cj;
                #pragma unroll
                for (int rp2 = 0; rp2 < 4; ++rp2)
                    *(ull*)(rp_ + c * 72 + r0 + rp2 * 2) = acc[(cjbase + cj) * 4 + rp2];
            }
        }
        __syncthreads();
        // LSTM pointwise (threads 0..255)
        if (tid < 256) {
            float gv[4];
            #pragma unroll
            for (int gg = 0; gg < 4; ++gg) {
                const float* q = red + ((gg << 2) + e_nn) * 72 + e_b;
                float v = bias[gg];
                #pragma unroll
                for (int pp = 0; pp < 16; ++pp) v += q[pp * 1152];
                gv[gg] = v;
            }
            int n = n0_1 + e_nn;
            float cold = __ldcg(&g_c[n * 64 + e_b]);
            float cv = sigm(gv[1]) * cold + sigm(gv[0]) * tanhf(gv[2]);
            float hv = sigm(gv[3]) * tanhf(cv);
            g_cn[n * 64 + e_b] = cv;
            g_hn[n * 64 + e_b] = hv;
        }
        grid_bar();

        // ================= stage 2: 8 windows of 64 k ========================
        #pragma unroll
        for (int i = 0; i < 32; ++i) acc[i] = 0ull;
        if (s + 1 < Sn) {   // L2 prefetch of next step's x
            const float* nx = g_xT + (size_t)(s + 1) * 32768 + tid * 64;
            asm volatile("prefetch.global.L2 [%0];" :: "l"(nx));
            asm volatile("prefetch.global.L2 [%0];" :: "l"(nx + 32));
        }
        {
            const float4* src = (const float4*)Asrc2;
            pre0 = __ldcg(src + tid); pre1 = __ldcg(src + tid + 512);
            float4* dst = (float4*)Aw;
            dst[tid] = pre0; dst[tid + 512] = pre1;
            src = (const float4*)(Asrc2 + 4096);
            pre0 = __ldcg(src + tid); pre1 = __ldcg(src + tid + 512);
        }
        __syncthreads();
        for (int w = 0; w < 8; ++w) {
            if (w + 1 < 8) {
                float4* dst = (float4*)(Aw + ((w + 1) & 1) * 4096);
                dst[tid] = pre0; dst[tid + 512] = pre1;
            }
            if (w + 2 < 8) {
                const float4* src = (const float4*)(Asrc2 + (size_t)(w + 2) * 4096);
                pre0 = __ldcg(src + tid); pre1 = __ldcg(src + tid + 512);
            }
            const float* Ab = Aw + (w & 1) * 4096;
            #pragma unroll
            for (int j = 0; j < 2; ++j) {
                int kl = j * 32 + g;
                const float* ar = Ab + kl * 64 + r0;
                ulonglong2 aA = *(const ulonglong2*)ar;
                ulonglong2 aB = *(const ulonglong2*)(ar + 4);
                const float* wr = sW2 + (w * 64 + kl) * 16 + c0;
                float4 w0v = *(const float4*)wr;
                float4 w1v = *(const float4*)(wr + 4);
                float wc[8] = {w0v.x, w0v.y, w0v.z, w0v.w, w1v.x, w1v.y, w1v.z, w1v.w};
                #pragma unroll
                for (int cj = 0; cj < 8; ++cj) {
                    ull wp = pack2(wc[cj], wc[cj]);
                    acc[cj * 4 + 0] = fma2(aA.x, wp, acc[cj * 4 + 0]);
                    acc[cj * 4 + 1] = fma2(aA.y, wp, acc[cj * 4 + 1]);
                    acc[cj * 4 + 2] = fma2(aB.x, wp, acc[cj * 4 + 2]);
                    acc[cj * 4 + 3] = fma2(aB.y, wp, acc[cj * 4 + 3]);
                }
            }
            __syncthreads();
        }
        #pragma unroll
        for (int i = 0; i < 32; ++i) {
            ull o = __shfl_xor_sync(0xffffffffu, acc[i], 16);
            acc[i] = add2(acc[i], o);
        }
        {
            float* rp_ = red + p * 1152;
            #pragma unroll
            for (int cj = 0; cj < 4; ++cj) {
                int c = c0 + cjbase + cj;
                #pragma unroll
                for (int rp2 = 0; rp2 < 4; ++rp2)
                    *(ull*)(rp_ + c * 72 + r0 + rp2 * 2) = acc[(cjbase + cj) * 4 + rp2];
            }
        }
        __syncthreads();
        // sample epilogue: one (b, n) per thread
        {
            int b = e2_b;
            const float* qm = red + e2_nn * 72 + b;
            const float* qs = red + (8 + e2_nn) * 72 + b;
            float pm = 0.f, ps = 0.f;
            #pragma unroll
            for (int pp = 0; pp < 16; ++pp) { pm += qm[pp * 1152]; ps += qs[pp * 1152]; }
            float mu = fminf(fmaxf(pm, 1e-6f), 1e6f);
            float sd = fmaxf(softplus(ps), 1e-6f);
            int n = n0_2 + e2_nn;
            float e = epsP[(size_t)(s + 1) * BH + (size_t)b * 512 + n];
            float smp = fmaf(e, sd, mu);
            Sdst[n * 64 + b] = smp;
            size_t o = (size_t)b * 262656 + (size_t)(s + 1) * 512 + n;
            out[muB + o] = mu;
            out[sdB + o] = sd;
            if (isH) out[O_HID + (size_t)b * 262144 + (size_t)s * 512 + n] = smp;
            if (s == Sn - 1) out[tB + (size_t)b * 512 + n] = smp;
        }
        grid_bar();
    }
}

extern "C" void kernel_launch(void* const* d_in, const int* in_sizes, int n_in,
                              void* d_out, int out_size) {
    (void)in_sizes; (void)n_in; (void)out_size;
    const float* x    = (const float*)d_in[0];
    const float* W_ih = (const float*)d_in[1];
    const float* W_hh = (const float*)d_in[2];
    const float* b_ih = (const float*)d_in[3];
    const float* b_hh = (const float*)d_in[4];
    const float* W_hg = (const float*)d_in[5];
    const float* W_cg = (const float*)d_in[6];
    const float* eps_h = (const float*)d_in[7];
    const float* eps_c = (const float*)d_in[8];
    float* out = (float*)d_out;

    dim3 tg(512, 16, 2), tb(32, 8);
    xT_kernel<<<tg, tb>>>(x);

    cudaFuncSetAttribute(rglstm, cudaFuncAttributeMaxDynamicSharedMemorySize, SMEM_BYTES);
    rglstm<<<NBLK, NTHR, SMEM_BYTES>>>(W_ih, W_hh, b_ih, b_hh,
                                       W_hg, W_cg, eps_h, eps_c, out);
}

// round 7
// speedup vs baseline: 1.0024x; 1.0024x over previous
#include <cuda_runtime.h>
#include <math.h>

#define NBLK 128
#define NTHR 512

#define Bn 64
#define Hn 512
#define Sn 512
#define BH (Bn*Hn)         // 32768

typedef unsigned long long ull;

// output section offsets (floats)
#define O_HID   0ull
#define O_HMU   16777216ull
#define O_HSTD  33587200ull
#define O_CMU   50397184ull
#define O_CSTD  67207168ull
#define O_HT    84017152ull
#define O_CT    84049920ull

// persistent state, [n][b] layout (b contiguous)
__device__ float g_h[BH], g_c[BH], g_hn[BH], g_cn[BH];
__device__ float g_xT[(size_t)Sn * 512 * 64];   // [s][k][b]
__device__ unsigned g_cnt = 0;
__device__ volatile unsigned g_gen = 0;

__device__ __forceinline__ void grid_bar() {
    __syncthreads();
    if (threadIdx.x == 0) {
        __threadfence();
        unsigned gen = g_gen;
        if (atomicAdd(&g_cnt, 1u) == NBLK - 1) {
            g_cnt = 0;
            __threadfence();
            g_gen = gen + 1;
        } else {
            while (g_gen == gen) { }
            __threadfence();
        }
    }
    __syncthreads();
}

__device__ __forceinline__ float sigm(float v) { return 1.0f / (1.0f + expf(-v)); }
__device__ __forceinline__ float softplus(float v) {
    return fmaxf(v, 0.0f) + log1pf(expf(-fabsf(v)));
}

__device__ __forceinline__ ull pack2(float a, float b) {
    ull r; asm("mov.b64 %0, {%1, %2};" : "=l"(r) : "f"(a), "f"(b)); return r;
}
__device__ __forceinline__ ull fma2(ull a, ull b, ull c) {
    ull d; asm("fma.rn.f32x2 %0, %1, %2, %3;" : "=l"(d) : "l"(a), "l"(b), "l"(c)); return d;
}
__device__ __forceinline__ ull add2(ull a, ull b) {
    ull d; asm("add.rn.f32x2 %0, %1, %2;" : "=l"(d) : "l"(a), "l"(b)); return d;
}

// one-time x transpose: x[b][s][k] -> g_xT[s][k][b]
__global__ void xT_kernel(const float* __restrict__ x) {
    __shared__ float t[32][33];
    int s = blockIdx.x, k0 = blockIdx.y << 5, b0 = blockIdx.z << 5;
    int tx = threadIdx.x, ty = threadIdx.y;
    for (int bb = ty; bb < 32; bb += 8)
        t[bb][tx] = x[((size_t)(b0 + bb) * Sn + s) * 512 + k0 + tx];
    __syncthreads();
    for (int kk = ty; kk < 32; kk += 8)
        g_xT[((size_t)s * 512 + k0 + kk) * 64 + b0 + tx] = t[tx][kk];
}

// SMEM (floats): sW1 16384 | sW2 8192 | region: Aw(2x4096) aliased with red(16x1152)
#define SM_W2 16384
#define SM_RG 24576
#define SMEM_FLOATS (24576 + 18432)
#define SMEM_BYTES (SMEM_FLOATS * 4)

__global__ __launch_bounds__(NTHR, 1)
void rglstm(const float* __restrict__ W_ih, const float* __restrict__ W_hh,
            const float* __restrict__ b_ih, const float* __restrict__ b_hh,
            const float* __restrict__ W_hg, const float* __restrict__ W_cg,
            const float* __restrict__ eps_h, const float* __restrict__ eps_c,
            float* __restrict__ out)
{
    extern __shared__ float smem[];
    float* sW1 = smem;
    float* sW2 = smem + SM_W2;
    float* Aw  = smem + SM_RG;   // 2 x [64][64]
    float* red = smem + SM_RG;   // [16][16*72]  (alias, disjoint in time)

    const int tid = threadIdx.x;
    const int cb  = blockIdx.x;
    const bool isH = cb < 64;
    const int n0_1 = cb << 2;            // stage1: 4 hidden cols x 4 gates
    const int n0_2 = (cb & 63) << 3;     // stage2: 8 hidden cols (mu+std)

    // compute geometry: 32 k-groups x 16 tile-threads; tile 8r x 8c
    const int g  = tid >> 4;
    const int tt = tid & 15;
    const int r0 = (tt >> 1) << 3;       // 0,8,...,56
    const int c0 = (tt & 1) << 3;        // 0 or 8
    const int lane = tid & 31;
    const int p  = tid >> 5;             // partial slot = warp id (0..15)
    const int cjbase = (lane >= 16) ? 4 : 0;

    // ---- persistent weight slices into SMEM ----
    for (int i = tid; i < 16 * 1024; i += NTHR) {
        int c = i >> 10, k = i & 1023;
        int gcol = ((c >> 2) << 9) + n0_1 + (c & 3);
        sW1[k * 16 + c] = (k < 512) ? W_ih[gcol * 512 + k] : W_hh[gcol * 512 + (k - 512)];
    }
    const float* Wg = isH ? W_hg : W_cg;
    for (int i = tid; i < 16 * 512; i += NTHR) {
        int k = i >> 4, c = i & 15;
        int pcol = (c < 8) ? (n0_2 + c) : (512 + n0_2 + (c - 8));
        sW2[k * 16 + c] = Wg[k * 1024 + pcol];
    }

    // epilogue-1 geometry + biases (threads 0..255)
    const int e_b  = tid & 63;
    const int e_nn = (tid >> 6) & 3;
    float bias[4];
    #pragma unroll
    for (int gg = 0; gg < 4; ++gg) {
        int gcol = (gg << 9) + n0_1 + e_nn;
        bias[gg] = b_ih[gcol] + b_hh[gcol];
    }
    // epilogue-2 geometry
    const int e2_nn = tid & 7;
    const int e2_b  = tid >> 3;          // 0..63

    // ---- t=0 init ----
    if (tid < 256) {
        const float LN2 = 0.693147180559945309f;
        int i = cb * 256 + tid;          // 0..32767 = n*64+b
        int b = i & 63, n = i >> 6;
        g_h[i] = fmaf(eps_h[(size_t)b * 512 + n], LN2, 1e-6f);
        g_c[i] = fmaf(eps_c[(size_t)b * 512 + n], LN2, 1e-6f);
        size_t o = (size_t)b * 262656 + n;
        out[O_HMU  + o] = 1e-6f;
        out[O_HSTD + o] = LN2;
        out[O_CMU  + o] = 1e-6f;
        out[O_CSTD + o] = LN2;
    }
    grid_bar();

    const float* Asrc2  = isH ? g_hn  : g_cn;
    float*       Sdst   = isH ? g_h   : g_c;
    const float* epsP   = isH ? eps_h : eps_c;
    const size_t muB = isH ? O_HMU  : O_CMU;
    const size_t sdB = isH ? O_HSTD : O_CSTD;
    const size_t tB  = isH ? O_HT   : O_CT;

    for (int s = 0; s < Sn; ++s) {
        ull acc[32];

        // ================= stage 1: 16 windows of 64 k (w<8: x, w>=8: h) ======
        #pragma unroll
        for (int i = 0; i < 32; ++i) acc[i] = 0ull;
        const float* xbase = g_xT + (size_t)s * 32768;

        float4 pre0, pre1;
        {   // prologue: window 0 -> buf0; window 1 -> regs
            const float4* src = (const float4*)xbase;
            pre0 = __ldcg(src + tid); pre1 = __ldcg(src + tid + 512);
            float4* dst = (float4*)Aw;
            dst[tid] = pre0; dst[tid + 512] = pre1;
            src = (const float4*)(xbase + 4096);
            pre0 = __ldcg(src + tid); pre1 = __ldcg(src + tid + 512);
        }
        __syncthreads();
        for (int w = 0; w < 16; ++w) {
            if (w + 1 < 16) {
                float4* dst = (float4*)(Aw + ((w + 1) & 1) * 4096);
                dst[tid] = pre0; dst[tid + 512] = pre1;
            }
            if (w + 2 < 16) {
                const float4* src = (w + 2 < 8)
                    ? (const float4*)(xbase + (size_t)(w + 2) * 4096)
                    : (const float4*)(g_h + (w + 2 - 8) * 4096);
                pre0 = __ldcg(src + tid); pre1 = __ldcg(src + tid + 512);
            }
            const float* Ab = Aw + (w & 1) * 4096;
            #pragma unroll
            for (int j = 0; j < 2; ++j) {
                int kl = j * 32 + g;
                const float* ar = Ab + kl * 64 + r0;
                ulonglong2 aA = *(const ulonglong2*)ar;
                ulonglong2 aB = *(const ulonglong2*)(ar + 4);
                const float* wr = sW1 + (w * 64 + kl) * 16 + c0;
                float4 w0v = *(const float4*)wr;
                float4 w1v = *(const float4*)(wr + 4);
                float wc[8] = {w0v.x, w0v.y, w0v.z, w0v.w, w1v.x, w1v.y, w1v.z, w1v.w};
                #pragma unroll
                for (int cj = 0; cj < 8; ++cj) {
                    ull wp = pack2(wc[cj], wc[cj]);
                    acc[cj * 4 + 0] = fma2(aA.x, wp, acc[cj * 4 + 0]);
                    acc[cj * 4 + 1] = fma2(aA.y, wp, acc[cj * 4 + 1]);
                    acc[cj * 4 + 2] = fma2(aB.x, wp, acc[cj * 4 + 2]);
                    acc[cj * 4 + 3] = fma2(aB.y, wp, acc[cj * 4 + 3]);
                }
            }
            __syncthreads();
        }
        // fold paired k-groups, write 16 partials
        #pragma unroll
        for (int i = 0; i < 32; ++i) {
            ull o = __shfl_xor_sync(0xffffffffu, acc[i], 16);
            acc[i] = add2(acc[i], o);
        }
        {
            float* rp_ = red + p * 1152;
            #pragma unroll
            for (int cj = 0; cj < 4; ++cj) {
                int c = c0 + cjbase + cj;
                #pragma unroll
                for (int rp2 = 0; rp2 < 4; ++rp2)
                    *(ull*)(rp_ + c * 72 + r0 + rp2 * 2) = acc[(cjbase + cj) * 4 + rp2];
            }
        }
        __syncthreads();
        // LSTM pointwise (threads 0..255)
        if (tid < 256) {
            float gv[4];
            #pragma unroll
            for (int gg = 0; gg < 4; ++gg) {
                const float* q = red + ((gg << 2) + e_nn) * 72 + e_b;
                float v = bias[gg];
                #pragma unroll
                for (int pp = 0; pp < 16; ++pp) v += q[pp * 1152];
                gv[gg] = v;
            }
            int n = n0_1 + e_nn;
            float cold = __ldcg(&g_c[n * 64 + e_b]);
            float cv = sigm(gv[1]) * cold + sigm(gv[0]) * tanhf(gv[2]);
            float hv = sigm(gv[3]) * tanhf(cv);
            g_cn[n * 64 + e_b] = cv;
            g_hn[n * 64 + e_b] = hv;
        }
        grid_bar();

        // ================= stage 2: 8 windows of 64 k ========================
        #pragma unroll
        for (int i = 0; i < 32; ++i) acc[i] = 0ull;
        if (s + 1 < Sn) {   // L2 prefetch of next step's x
            const float* nx = g_xT + (size_t)(s + 1) * 32768 + tid * 64;
            asm volatile("prefetch.global.L2 [%0];" :: "l"(nx));
            asm volatile("prefetch.global.L2 [%0];" :: "l"(nx + 32));
        }
        {
            const float4* src = (const float4*)Asrc2;
            pre0 = __ldcg(src + tid); pre1 = __ldcg(src + tid + 512);
            float4* dst = (float4*)Aw;
            dst[tid] = pre0; dst[tid + 512] = pre1;
            src = (const float4*)(Asrc2 + 4096);
            pre0 = __ldcg(src + tid); pre1 = __ldcg(src + tid + 512);
        }
        __syncthreads();
        for (int w = 0; w < 8; ++w) {
            if (w + 1 < 8) {
                float4* dst = (float4*)(Aw + ((w + 1) & 1) * 4096);
                dst[tid] = pre0; dst[tid + 512] = pre1;
            }
            if (w + 2 < 8) {
                const float4* src = (const float4*)(Asrc2 + (size_t)(w + 2) * 4096);
                pre0 = __ldcg(src + tid); pre1 = __ldcg(src + tid + 512);
            }
            const float* Ab = Aw + (w & 1) * 4096;
            #pragma unroll
            for (int j = 0; j < 2; ++j) {
                int kl = j * 32 + g;
                const float* ar = Ab + kl * 64 + r0;
                ulonglong2 aA = *(const ulonglong2*)ar;
                ulonglong2 aB = *(const ulonglong2*)(ar + 4);
                const float* wr = sW2 + (w * 64 + kl) * 16 + c0;
                float4 w0v = *(const float4*)wr;
                float4 w1v = *(const float4*)(wr + 4);
                float wc[8] = {w0v.x, w0v.y, w0v.z, w0v.w, w1v.x, w1v.y, w1v.z, w1v.w};
                #pragma unroll
                for (int cj = 0; cj < 8; ++cj) {
                    ull wp = pack2(wc[cj], wc[cj]);
                    acc[cj * 4 + 0] = fma2(aA.x, wp, acc[cj * 4 + 0]);
                    acc[cj * 4 + 1] = fma2(aA.y, wp, acc[cj * 4 + 1]);
                    acc[cj * 4 + 2] = fma2(aB.x, wp, acc[cj * 4 + 2]);
                    acc[cj * 4 + 3] = fma2(aB.y, wp, acc[cj * 4 + 3]);
                }
            }
            __syncthreads();
        }
        #pragma unroll
        for (int i = 0; i < 32; ++i) {
            ull o = __shfl_xor_sync(0xffffffffu, acc[i], 16);
            acc[i] = add2(acc[i], o);
        }
        {
            float* rp_ = red + p * 1152;
            #pragma unroll
            for (int cj = 0; cj < 4; ++cj) {
                int c = c0 + cjbase + cj;
                #pragma unroll
                for (int rp2 = 0; rp2 < 4; ++rp2)
                    *(ull*)(rp_ + c * 72 + r0 + rp2 * 2) = acc[(cjbase + cj) * 4 + rp2];
            }
        }
        __syncthreads();
        // sample epilogue: one (b, n) per thread
        {
            int b = e2_b;
            const float* qm = red + e2_nn * 72 + b;
            const float* qs = red + (8 + e2_nn) * 72 + b;
            float pm = 0.f, ps = 0.f;
            #pragma unroll
            for (int pp = 0; pp < 16; ++pp) { pm += qm[pp * 1152]; ps += qs[pp * 1152]; }
            float mu = fminf(fmaxf(pm, 1e-6f), 1e6f);
            float sd = fmaxf(softplus(ps), 1e-6f);
            int n = n0_2 + e2_nn;
            float e = epsP[(size_t)(s + 1) * BH + (size_t)b * 512 + n];
            float smp = fmaf(e, sd, mu);
            Sdst[n * 64 + b] = smp;
            size_t o = (size_t)b * 262656 + (size_t)(s + 1) * 512 + n;
            out[muB + o] = mu;
            out[sdB + o] = sd;
            if (isH) out[O_HID + (size_t)b * 262144 + (size_t)s * 512 + n] = smp;
            if (s == Sn - 1) out[tB + (size_t)b * 512 + n] = smp;
        }
        grid_bar();
    }
}

extern "C" void kernel_launch(void* const* d_in, const int* in_sizes, int n_in,
                              void* d_out, int out_size) {
    (void)in_sizes; (void)n_in; (void)out_size;
    const float* x    = (const float*)d_in[0];
    const float* W_ih = (const float*)d_in[1];
    const float* W_hh = (const float*)d_in[2];
    const float* b_ih = (const float*)d_in[3];
    const float* b_hh = (const float*)d_in[4];
    const float* W_hg = (const float*)d_in[5];
    const float* W_cg = (const float*)d_in[6];
    const float* eps_h = (const float*)d_in[7];
    const float* eps_c = (const float*)d_in[8];
    float* out = (float*)d_out;

    dim3 tg(512, 16, 2), tb(32, 8);
    xT_kernel<<<tg, tb>>>(x);

    cudaFuncSetAttribute(rglstm, cudaFuncAttributeMaxDynamicSharedMemorySize, SMEM_BYTES);
    rglstm<<<NBLK, NTHR, SMEM_BYTES>>>(W_ih, W_hh, b_ih, b_hh,
                                       W_hg, W_cg, eps_h, eps_c, out);
}

// round 9
// speedup vs baseline: 1.2145x; 1.2116x over previous
#include <cuda_runtime.h>
#include <cuda_bf16.h>
#include <math.h>

#define NBLK 128
#define NTHR 256
#define Bn 64
#define Sn 512
#define BH 32768

typedef unsigned u32;
typedef unsigned long long u64;

// output section offsets (floats)
#define O_HID   0ull
#define O_HMU   16777216ull
#define O_HSTD  33587200ull
#define O_CMU   50397184ull
#define O_CSTD  67207168ull
#define O_HT    84017152ull
#define O_CT    84049920ull

// global state (bf16 hi/lo splits; [b][*] layouts)
__device__ __nv_bfloat16 g_xh[(size_t)Bn*Sn*512];   // [b][s][k]
__device__ __nv_bfloat16 g_xl[(size_t)Bn*Sn*512];
__device__ __nv_bfloat16 g_hh[BH], g_hl[BH];        // sampled h [b][n]
__device__ __nv_bfloat16 g_nhh[BH], g_nhl[BH];      // h_new
__device__ __nv_bfloat16 g_nch[BH], g_ncl[BH];      // c_new
__device__ float g_cs[BH];                          // sampled c (fp32)
__device__ unsigned g_cnt = 0;
__device__ volatile unsigned g_gen = 0;

__device__ __forceinline__ void grid_bar() {
    __syncthreads();
    if (threadIdx.x == 0) {
        __threadfence();
        unsigned gen = g_gen;
        if (atomicAdd(&g_cnt, 1u) == NBLK - 1) {
            g_cnt = 0;
            __threadfence();
            g_gen = gen + 1;
        } else {
            while (g_gen == gen) { }
            __threadfence();
        }
    }
    __syncthreads();
}

__device__ __forceinline__ float sigm(float v) { return 1.0f / (1.0f + expf(-v)); }
__device__ __forceinline__ float softplus(float v) {
    return fmaxf(v, 0.0f) + log1pf(expf(-fabsf(v)));
}

// ---------- PTX helpers (all sm_80+, legal on compute_100) ----------
__device__ __forceinline__ u32 smem_u32(const void* p) {
    u32 a;
    asm("{ .reg .u64 t; cvta.to.shared.u64 t, %1; cvt.u32.u64 %0, t; }" : "=r"(a) : "l"(p));
    return a;
}
__device__ __forceinline__ void cpa16(u32 dst, const void* src) {
    asm volatile("cp.async.cg.shared.global [%0], [%1], 16;" :: "r"(dst), "l"(src));
}
__device__ __forceinline__ void cpa_commit() {
    asm volatile("cp.async.commit_group;" ::: "memory");
}
template <int N> __device__ __forceinline__ void cpa_wait() {
    asm volatile("cp.async.wait_group %0;" :: "n"(N) : "memory");
}
__device__ __forceinline__ void ldm4(u32* r, u32 addr) {
    asm volatile("ldmatrix.sync.aligned.m8n8.x4.shared.b16 {%0,%1,%2,%3}, [%4];"
                 : "=r"(r[0]), "=r"(r[1]), "=r"(r[2]), "=r"(r[3]) : "r"(addr));
}
__device__ __forceinline__ void lds2(u32& x, u32& y, u32 a) {
    asm volatile("ld.shared.v2.b32 {%0,%1}, [%2];" : "=r"(x), "=r"(y) : "r"(a));
}
__device__ __forceinline__ void mma16816(float* d, const u32* a, u32 b0, u32 b1) {
    asm volatile(
        "mma.sync.aligned.m16n8k16.row.col.f32.bf16.bf16.f32 "
        "{%0,%1,%2,%3}, {%4,%5,%6,%7}, {%8,%9}, {%0,%1,%2,%3};"
        : "+f"(d[0]), "+f"(d[1]), "+f"(d[2]), "+f"(d[3])
        : "r"(a[0]), "r"(a[1]), "r"(a[2]), "r"(a[3]), "r"(b0), "r"(b1));
}
__device__ __forceinline__ u32 hpair(__nv_bfloat16 a, __nv_bfloat16 b) {
    unsigned short ua = *(unsigned short*)&a, ub = *(unsigned short*)&b;
    return (u32)ua | ((u32)ub << 16);
}

// SMEM map (bytes)
#define SO_W1H  0
#define SO_W1L  32768
#define SO_W2H  65536
#define SO_W2L  81920
#define SO_A    98304
#define ABUF    34816      // per buffer: h [64][272B] + l at +17408
#define AST     272
#define SO_DP   167936     // 2 x 64 x 18 f32
#define SO_B1   177152
#define SMEM_BYTES 177280

// one-time x split
__global__ void xsplit_kernel(const float* __restrict__ x) {
    size_t i = (size_t)blockIdx.x * 256 + threadIdx.x;
    float v = x[i];
    __nv_bfloat16 hi = __float2bfloat16(v);
    g_xh[i] = hi;
    g_xl[i] = __float2bfloat16(v - __bfloat162float(hi));
}

__global__ __launch_bounds__(NTHR, 1)
void rglstm(const float* __restrict__ W_ih, const float* __restrict__ W_hh,
            const float* __restrict__ b_ih, const float* __restrict__ b_hh,
            const float* __restrict__ W_hg, const float* __restrict__ W_cg,
            const float* __restrict__ eps_h, const float* __restrict__ eps_c,
            float* __restrict__ out)
{
    extern __shared__ char smem8[];
    float* sB1 = (float*)(smem8 + SO_B1);
    float* Dp  = (float*)(smem8 + SO_DP);     // [2][64][18]

    const int tid  = threadIdx.x;
    const int wid  = tid >> 5;
    const int lane = tid & 31;
    const int cb   = blockIdx.x;
    const bool isH = cb < 64;
    const int n0_1 = cb << 2;
    const int n0_2 = (cb & 63) << 3;

    const u32 sb  = smem_u32(smem8);
    const u32 sbA = sb + SO_A;

    const int mt    = wid & 3;
    const int khalf = wid >> 2;
    // ldmatrix lane row offset (bytes) and col-half (bytes)
    const u32 aRow  = (u32)((mt * 16 + (lane & 7) + ((lane >> 3) & 1) * 8) * AST);
    const u32 aColH = (u32)(((lane >> 4) & 1) * 16);

    // loader geometry
    const int lrow = tid >> 2;
    const int lq   = tid & 3;

    // ---- weight fragments (hi/lo), fragment-order SMEM ----
    for (int i = tid; i < 4096; i += NTHR) {          // W1: 128 frags x 32 lanes
        int fr = i >> 5, l = i & 31;
        int ktg = fr >> 1, nt = fr & 1;
        int nl = nt * 8 + (l >> 2);
        int gcol = (nl >> 2) * 512 + n0_1 + (nl & 3);
        int k0 = ktg * 16 + 2 * (l & 3);
        const float* base = (k0 < 512) ? (W_ih + gcol * 512) : (W_hh + gcol * 512 - 512);
        float w00 = base[k0], w01 = base[k0 + 1], w08 = base[k0 + 8], w09 = base[k0 + 9];
        __nv_bfloat16 h00 = __float2bfloat16(w00), h01 = __float2bfloat16(w01);
        __nv_bfloat16 h08 = __float2bfloat16(w08), h09 = __float2bfloat16(w09);
        u32 off = (u32)(fr * 256 + l * 8);
        *(u32*)(smem8 + SO_W1H + off)     = hpair(h00, h01);
        *(u32*)(smem8 + SO_W1H + off + 4) = hpair(h08, h09);
        *(u32*)(smem8 + SO_W1L + off)     = hpair(__float2bfloat16(w00 - __bfloat162float(h00)),
                                                  __float2bfloat16(w01 - __bfloat162float(h01)));
        *(u32*)(smem8 + SO_W1L + off + 4) = hpair(__float2bfloat16(w08 - __bfloat162float(h08)),
                                                  __float2bfloat16(w09 - __bfloat162float(h09)));
    }
    {
        const float* Wg = isH ? W_hg : W_cg;
        for (int i = tid; i < 2048; i += NTHR) {      // W2: 64 frags x 32 lanes
            int fr = i >> 5, l = i & 31;
            int ktg = fr >> 1, nt = fr & 1;
            int nl = nt * 8 + (l >> 2);
            int pcol = (nl < 8) ? (n0_2 + nl) : (512 + n0_2 + (nl - 8));
            int k0 = ktg * 16 + 2 * (l & 3);
            float w00 = Wg[k0 * 1024 + pcol],       w01 = Wg[(k0 + 1) * 1024 + pcol];
            float w08 = Wg[(k0 + 8) * 1024 + pcol], w09 = Wg[(k0 + 9) * 1024 + pcol];
            __nv_bfloat16 h00 = __float2bfloat16(w00), h01 = __float2bfloat16(w01);
            __nv_bfloat16 h08 = __float2bfloat16(w08), h09 = __float2bfloat16(w09);
            u32 off = (u32)(fr * 256 + l * 8);
            *(u32*)(smem8 + SO_W2H + off)     = hpair(h00, h01);
            *(u32*)(smem8 + SO_W2H + off + 4) = hpair(h08, h09);
            *(u32*)(smem8 + SO_W2L + off)     = hpair(__float2bfloat16(w00 - __bfloat162float(h00)),
                                                      __float2bfloat16(w01 - __bfloat162float(h01)));
            *(u32*)(smem8 + SO_W2L + off + 4) = hpair(__float2bfloat16(w08 - __bfloat162float(h08)),
                                                      __float2bfloat16(w09 - __bfloat162float(h09)));
        }
    }
    if (tid < 16) {
        int gcol = (tid >> 2) * 512 + n0_1 + (tid & 3);
        sB1[tid] = b_ih[gcol] + b_hh[gcol];
    }

    // ---- t=0: z=0 -> mu=1e-6, std=ln2 ----
    {
        const float LN2 = 0.693147180559945309f;
        int i = cb * NTHR + tid;      // b*512+n over grid
        int b = i >> 9, n = i & 511;
        float hs = fmaf(eps_h[i], LN2, 1e-6f);
        float cs = fmaf(eps_c[i], LN2, 1e-6f);
        __nv_bfloat16 hh = __float2bfloat16(hs);
        g_hh[i] = hh;
        g_hl[i] = __float2bfloat16(hs - __bfloat162float(hh));
        g_cs[i] = cs;
        size_t o = (size_t)b * 262656 + n;
        out[O_HMU  + o] = 1e-6f;
        out[O_HSTD + o] = LN2;
        out[O_CMU  + o] = 1e-6f;
        out[O_CSTD + o] = LN2;
    }
    grid_bar();

    const float* epsP = isH ? eps_h : eps_c;
    const size_t muB = isH ? O_HMU  : O_CMU;
    const size_t sdB = isH ? O_HSTD : O_CSTD;
    const size_t tB  = isH ? O_HT   : O_CT;
    const __nv_bfloat16* s2H = isH ? g_nhh : g_nch;
    const __nv_bfloat16* s2L = isH ? g_nhl : g_ncl;

    // stage-1 pointwise geometry
    const int e_b  = tid & 63;
    const int e_nn = tid >> 6;
    // stage-2 epilogue geometry
    const int e2_j = tid & 7;
    const int e2_b = tid >> 3;     // 0..31

    for (int s = 0; s < Sn; ++s) {
        float acc[16];             // [kp][nt][4]

        // ---- loader lambda: chunk c (stage st) into buffer bf ----
        auto issue1 = [&](int c, int bf) {
            const char *gh, *gl;
            if (c < 4) {
                size_t o = ((size_t)lrow * Sn + s) * 512 + c * 128;
                gh = (const char*)(g_xh + o); gl = (const char*)(g_xl + o);
            } else {
                size_t o = (size_t)lrow * 512 + (c - 4) * 128;
                gh = (const char*)(g_hh + o); gl = (const char*)(g_hl + o);
            }
            u32 dh = sbA + (u32)(bf * ABUF + lrow * AST + lq * 64);
            #pragma unroll
            for (int u = 0; u < 4; ++u) {
                cpa16(dh + u * 16,         gh + lq * 64 + u * 16);
                cpa16(dh + 17408 + u * 16, gl + lq * 64 + u * 16);
            }
            cpa_commit();
        };
        auto issue2 = [&](int c, int bf) {
            size_t o = (size_t)lrow * 512 + c * 128;
            const char* gh = (const char*)(s2H + o);
            const char* gl = (const char*)(s2L + o);
            u32 dh = sbA + (u32)(bf * ABUF + lrow * AST + lq * 64);
            #pragma unroll
            for (int u = 0; u < 4; ++u) {
                cpa16(dh + u * 16,         gh + lq * 64 + u * 16);
                cpa16(dh + 17408 + u * 16, gl + lq * 64 + u * 16);
            }
            cpa_commit();
        };
        auto compute = [&](int bf, u32 wH, u32 wL, int ktgBase) {
            u32 ab = sbA + (u32)(bf * ABUF) + aRow + aColH + (u32)(khalf * 128);
            #pragma unroll
            for (int kt = 0; kt < 4; ++kt) {
                u32 ah[4], al[4];
                ldm4(ah, ab + kt * 32);
                ldm4(al, ab + kt * 32 + 17408);
                u32 wb = (u32)((ktgBase + kt) * 512 + lane * 8);
                u32 h0a, h0b, h1a, h1b, l0a, l0b, l1a, l1b;
                lds2(h0a, h0b, wH + wb);
                lds2(h1a, h1b, wH + wb + 256);
                lds2(l0a, l0b, wL + wb);
                lds2(l1a, l1b, wL + wb + 256);
                float* A0 = acc + (kt & 1) * 8;
                float* A1 = A0 + 4;
                mma16816(A0, ah, h0a, h0b);
                mma16816(A1, ah, h1a, h1b);
                mma16816(A0, ah, l0a, l0b);
                mma16816(A1, ah, l1a, l1b);
                mma16816(A0, al, h0a, h0b);
                mma16816(A1, al, h1a, h1b);
            }
        };
        auto storeDp = [&]() {
            // fold k-parity, write D partial [khalf][row][col]
            int rlo = mt * 16 + (lane >> 2);
            int cc  = 2 * (lane & 3);
            float* dp = Dp + khalf * 1152;
            #pragma unroll
            for (int nt = 0; nt < 2; ++nt) {
                float* A = acc + nt * 4;
                float d0 = A[0] + A[8], d1 = A[1] + A[9];
                float d2 = A[2] + A[10], d3 = A[3] + A[11];
                int c = nt * 8 + cc;
                dp[rlo * 18 + c]       = d0;
                dp[rlo * 18 + c + 1]   = d1;
                dp[(rlo + 8) * 18 + c]     = d2;
                dp[(rlo + 8) * 18 + c + 1] = d3;
            }
        };

        // ================= stage 1 (8 chunks) =================
        #pragma unroll
        for (int i = 0; i < 16; ++i) acc[i] = 0.f;
        issue1(0, 0); issue1(1, 1);
        cpa_wait<1>(); __syncthreads();
        for (int c = 0; c < 8; ++c) {
            compute(c & 1, sb + SO_W1H, sb + SO_W1L, c * 8 + khalf * 4);
            __syncthreads();
            if (c + 2 < 8) { issue1(c + 2, c & 1); cpa_commit(); }
            if (c + 1 < 8) {
                if (c + 2 < 8) cpa_wait<1>(); else cpa_wait<0>();
                __syncthreads();
            }
        }
        storeDp();
        __syncthreads();
        // LSTM pointwise: (b, nn) per thread
        {
            float gv[4];
            #pragma unroll
            for (int gg = 0; gg < 4; ++gg) {
                int c = gg * 4 + e_nn;
                gv[gg] = Dp[e_b * 18 + c] + Dp[1152 + e_b * 18 + c] + sB1[c];
            }
            int n = n0_1 + e_nn;
            float cold = __ldcg(&g_cs[e_b * 512 + n]);
            float cv = sigm(gv[1]) * cold + sigm(gv[0]) * tanhf(gv[2]);
            float hv = sigm(gv[3]) * tanhf(cv);
            __nv_bfloat16 ch = __float2bfloat16(cv);
            g_nch[e_b * 512 + n] = ch;
            g_ncl[e_b * 512 + n] = __float2bfloat16(cv - __bfloat162float(ch));
            __nv_bfloat16 hh2 = __float2bfloat16(hv);
            g_nhh[e_b * 512 + n] = hh2;
            g_nhl[e_b * 512 + n] = __float2bfloat16(hv - __bfloat162float(hh2));
        }
        grid_bar();

        // ================= stage 2 (4 chunks) =================
        #pragma unroll
        for (int i = 0; i < 16; ++i) acc[i] = 0.f;
        issue2(0, 0); issue2(1, 1);
        cpa_wait<1>(); __syncthreads();
        for (int c = 0; c < 4; ++c) {
            compute(c & 1, sb + SO_W2H, sb + SO_W2L, c * 8 + khalf * 4);
            __syncthreads();
            if (c + 2 < 4) { issue2(c + 2, c & 1); cpa_commit(); }
            if (c + 1 < 4) {
                if (c + 2 < 4) cpa_wait<1>(); else cpa_wait<0>();
                __syncthreads();
            }
        }
        storeDp();
        __syncthreads();
        // sample epilogue: 2 (b, n) per thread
        #pragma unroll
        for (int half = 0; half < 2; ++half) {
            int b = e2_b + half * 32;
            float pm = Dp[b * 18 + e2_j]       + Dp[1152 + b * 18 + e2_j];
            float ps = Dp[b * 18 + 8 + e2_j]   + Dp[1152 + b * 18 + 8 + e2_j];
            float mu = fminf(fmaxf(pm, 1e-6f), 1e6f);
            float sd = fmaxf(softplus(ps), 1e-6f);
            int n = n0_2 + e2_j;
            float e = epsP[(size_t)(s + 1) * BH + (size_t)b * 512 + n];
            float smp = fmaf(e, sd, mu);
            size_t o = (size_t)b * 262656 + (size_t)(s + 1) * 512 + n;
            out[muB + o] = mu;
            out[sdB + o] = sd;
            if (isH) {
                out[O_HID + (size_t)b * 262144 + (size_t)s * 512 + n] = smp;
                __nv_bfloat16 hh2 = __float2bfloat16(smp);
                g_hh[b * 512 + n] = hh2;
                g_hl[b * 512 + n] = __float2bfloat16(smp - __bfloat162float(hh2));
            } else {
                g_cs[b * 512 + n] = smp;
            }
            if (s == Sn - 1) out[tB + (size_t)b * 512 + n] = smp;
        }
        grid_bar();
    }
}

extern "C" void kernel_launch(void* const* d_in, const int* in_sizes, int n_in,
                              void* d_out, int out_size) {
    (void)in_sizes; (void)n_in; (void)out_size;
    const float* x    = (const float*)d_in[0];
    const float* W_ih = (const float*)d_in[1];
    const float* W_hh = (const float*)d_in[2];
    const float* b_ih = (const float*)d_in[3];
    const float* b_hh = (const float*)d_in[4];
    const float* W_hg = (const float*)d_in[5];
    const float* W_cg = (const float*)d_in[6];
    const float* eps_h = (const float*)d_in[7];
    const float* eps_c = (const float*)d_in[8];
    float* out = (float*)d_out;

    xsplit_kernel<<<65536, 256>>>(x);

    cudaFuncSetAttribute(rglstm, cudaFuncAttributeMaxDynamicSharedMemorySize, SMEM_BYTES);
    rglstm<<<NBLK, NTHR, SMEM_BYTES>>>(W_ih, W_hh, b_ih, b_hh,
                                       W_hg, W_cg, eps_h, eps_c, out);
}

// round 10
// speedup vs baseline: 1.8118x; 1.4919x over previous
#include <cuda_runtime.h>
#include <cuda_bf16.h>
#include <math.h>

#define NBLK 128
#define NTHR 512
#define Bn 64
#define Sn 512
#define BH 32768

typedef unsigned u32;
typedef unsigned long long u64;

// output section offsets (floats)
#define O_HID   0ull
#define O_HMU   16777216ull
#define O_HSTD  33587200ull
#define O_CMU   50397184ull
#define O_CSTD  67207168ull
#define O_HT    84017152ull
#define O_CT    84049920ull

// global state (bf16 hi/lo splits; [b][*] layouts)
__device__ __nv_bfloat16 g_xh[(size_t)Bn*Sn*512];   // [b][s][k]
__device__ __nv_bfloat16 g_xl[(size_t)Bn*Sn*512];
__device__ __nv_bfloat16 g_hh[BH], g_hl[BH];        // sampled h [b][n]
__device__ __nv_bfloat16 g_nhh[BH], g_nhl[BH];      // h_new
__device__ __nv_bfloat16 g_nch[BH], g_ncl[BH];      // c_new
__device__ float g_cs[BH];                          // sampled c (fp32)
__device__ unsigned g_cnt = 0;
__device__ volatile unsigned g_gen = 0;

__device__ __forceinline__ void grid_bar() {
    __syncthreads();
    if (threadIdx.x == 0) {
        __threadfence();
        unsigned gen = g_gen;
        if (atomicAdd(&g_cnt, 1u) == NBLK - 1) {
            g_cnt = 0;
            __threadfence();
            g_gen = gen + 1;
        } else {
            while (g_gen == gen) { }
            __threadfence();
        }
    }
    __syncthreads();
}

__device__ __forceinline__ float sigm(float v) { return 1.0f / (1.0f + expf(-v)); }
__device__ __forceinline__ float softplus(float v) {
    return fmaxf(v, 0.0f) + log1pf(expf(-fabsf(v)));
}

// ---------- PTX helpers (sm_80+, legal on compute_100) ----------
__device__ __forceinline__ u32 smem_u32(const void* p) {
    u32 a;
    asm("{ .reg .u64 t; cvta.to.shared.u64 t, %1; cvt.u32.u64 %0, t; }" : "=r"(a) : "l"(p));
    return a;
}
__device__ __forceinline__ void cpa16(u32 dst, const void* src) {
    asm volatile("cp.async.cg.shared.global [%0], [%1], 16;" :: "r"(dst), "l"(src));
}
__device__ __forceinline__ void cpa_commit() {
    asm volatile("cp.async.commit_group;" ::: "memory");
}
template <int N> __device__ __forceinline__ void cpa_wait() {
    asm volatile("cp.async.wait_group %0;" :: "n"(N) : "memory");
}
__device__ __forceinline__ void ldm4(u32* r, u32 addr) {
    asm volatile("ldmatrix.sync.aligned.m8n8.x4.shared.b16 {%0,%1,%2,%3}, [%4];"
                 : "=r"(r[0]), "=r"(r[1]), "=r"(r[2]), "=r"(r[3]) : "r"(addr));
}
__device__ __forceinline__ void lds2(u32& x, u32& y, u32 a) {
    asm volatile("ld.shared.v2.b32 {%0,%1}, [%2];" : "=r"(x), "=r"(y) : "r"(a));
}
__device__ __forceinline__ void mma16816(float* d, const u32* a, u32 b0, u32 b1) {
    asm volatile(
        "mma.sync.aligned.m16n8k16.row.col.f32.bf16.bf16.f32 "
        "{%0,%1,%2,%3}, {%4,%5,%6,%7}, {%8,%9}, {%0,%1,%2,%3};"
        : "+f"(d[0]), "+f"(d[1]), "+f"(d[2]), "+f"(d[3])
        : "r"(a[0]), "r"(a[1]), "r"(a[2]), "r"(a[3]), "r"(b0), "r"(b1));
}
__device__ __forceinline__ u32 hpair(__nv_bfloat16 a, __nv_bfloat16 b) {
    unsigned short ua = *(unsigned short*)&a, ub = *(unsigned short*)&b;
    return (u32)ua | ((u32)ub << 16);
}

// SMEM map (bytes)
#define SO_W1H  0
#define SO_W1L  32768
#define SO_W2H  65536
#define SO_W2L  81920
#define SO_A    98304
#define ABUF    34816      // per buffer: h [64][272B] + l at +17408
#define AST     272
#define SO_DP   202752     // 4 x 64 x 18 f32
#define SO_B1   221184
#define SMEM_BYTES 221248

// one-time x split
__global__ void xsplit_kernel(const float* __restrict__ x) {
    size_t i = (size_t)blockIdx.x * 256 + threadIdx.x;
    float v = x[i];
    __nv_bfloat16 hi = __float2bfloat16(v);
    g_xh[i] = hi;
    g_xl[i] = __float2bfloat16(v - __bfloat162float(hi));
}

__global__ __launch_bounds__(NTHR, 1)
void rglstm(const float* __restrict__ W_ih, const float* __restrict__ W_hh,
            const float* __restrict__ b_ih, const float* __restrict__ b_hh,
            const float* __restrict__ W_hg, const float* __restrict__ W_cg,
            const float* __restrict__ eps_h, const float* __restrict__ eps_c,
            float* __restrict__ out)
{
    extern __shared__ char smem8[];
    float* sB1 = (float*)(smem8 + SO_B1);
    float* Dp  = (float*)(smem8 + SO_DP);     // [4][64][18]

    const int tid  = threadIdx.x;
    const int wid  = tid >> 5;
    const int lane = tid & 31;
    const int cb   = blockIdx.x;
    const bool isH = cb < 64;
    const int n0_1 = cb << 2;
    const int n0_2 = (cb & 63) << 3;

    const u32 sb  = smem_u32(smem8);
    const u32 sbA = sb + SO_A;

    const int mt    = wid & 3;        // m-tile (16 rows)
    const int khalf = wid >> 2;       // K quarter of each 128-k chunk (0..3)
    const u32 aRow  = (u32)((mt * 16 + (lane & 7) + ((lane >> 3) & 1) * 8) * AST);
    const u32 aColH = (u32)(((lane >> 4) & 1) * 16);

    // loader geometry: 64 rows x 8 threads x 32B (x2 for h/l)
    const int lrow = tid >> 3;
    const u32 lq32 = (u32)((tid & 7) << 5);

    // ---- weight fragments (hi/lo), fragment-order SMEM ----
    for (int i = tid; i < 4096; i += NTHR) {          // W1: 128 frags x 32 lanes
        int fr = i >> 5, l = i & 31;
        int ktg = fr >> 1, nt = fr & 1;
        int nl = nt * 8 + (l >> 2);
        int gcol = (nl >> 2) * 512 + n0_1 + (nl & 3);
        int k0 = ktg * 16 + 2 * (l & 3);
        const float* base = (k0 < 512) ? (W_ih + gcol * 512) : (W_hh + gcol * 512 - 512);
        float w00 = base[k0], w01 = base[k0 + 1], w08 = base[k0 + 8], w09 = base[k0 + 9];
        __nv_bfloat16 h00 = __float2bfloat16(w00), h01 = __float2bfloat16(w01);
        __nv_bfloat16 h08 = __float2bfloat16(w08), h09 = __float2bfloat16(w09);
        u32 off = (u32)(fr * 256 + l * 8);
        *(u32*)(smem8 + SO_W1H + off)     = hpair(h00, h01);
        *(u32*)(smem8 + SO_W1H + off + 4) = hpair(h08, h09);
        *(u32*)(smem8 + SO_W1L + off)     = hpair(__float2bfloat16(w00 - __bfloat162float(h00)),
                                                  __float2bfloat16(w01 - __bfloat162float(h01)));
        *(u32*)(smem8 + SO_W1L + off + 4) = hpair(__float2bfloat16(w08 - __bfloat162float(h08)),
                                                  __float2bfloat16(w09 - __bfloat162float(h09)));
    }
    {
        const float* Wg = isH ? W_hg : W_cg;
        for (int i = tid; i < 2048; i += NTHR) {      // W2: 64 frags x 32 lanes
            int fr = i >> 5, l = i & 31;
            int ktg = fr >> 1, nt = fr & 1;
            int nl = nt * 8 + (l >> 2);
            int pcol = (nl < 8) ? (n0_2 + nl) : (512 + n0_2 + (nl - 8));
            int k0 = ktg * 16 + 2 * (l & 3);
            float w00 = Wg[k0 * 1024 + pcol],       w01 = Wg[(k0 + 1) * 1024 + pcol];
            float w08 = Wg[(k0 + 8) * 1024 + pcol], w09 = Wg[(k0 + 9) * 1024 + pcol];
            __nv_bfloat16 h00 = __float2bfloat16(w00), h01 = __float2bfloat16(w01);
            __nv_bfloat16 h08 = __float2bfloat16(w08), h09 = __float2bfloat16(w09);
            u32 off = (u32)(fr * 256 + l * 8);
            *(u32*)(smem8 + SO_W2H + off)     = hpair(h00, h01);
            *(u32*)(smem8 + SO_W2H + off + 4) = hpair(h08, h09);
            *(u32*)(smem8 + SO_W2L + off)     = hpair(__float2bfloat16(w00 - __bfloat162float(h00)),
                                                      __float2bfloat16(w01 - __bfloat162float(h01)));
            *(u32*)(smem8 + SO_W2L + off + 4) = hpair(__float2bfloat16(w08 - __bfloat162float(h08)),
                                                      __float2bfloat16(w09 - __bfloat162float(h09)));
        }
    }
    if (tid < 16) {
        int gcol = (tid >> 2) * 512 + n0_1 + (tid & 3);
        sB1[tid] = b_ih[gcol] + b_hh[gcol];
    }

    // ---- t=0: z=0 -> mu=1e-6, std=ln2 ----
    if (tid < 256) {
        const float LN2 = 0.693147180559945309f;
        int i = cb * 256 + tid;       // b*512+n over grid
        int b = i >> 9, n = i & 511;
        float hs = fmaf(eps_h[i], LN2, 1e-6f);
        float cs = fmaf(eps_c[i], LN2, 1e-6f);
        __nv_bfloat16 hh = __float2bfloat16(hs);
        g_hh[i] = hh;
        g_hl[i] = __float2bfloat16(hs - __bfloat162float(hh));
        g_cs[i] = cs;
        size_t o = (size_t)b * 262656 + n;
        out[O_HMU  + o] = 1e-6f;
        out[O_HSTD + o] = LN2;
        out[O_CMU  + o] = 1e-6f;
        out[O_CSTD + o] = LN2;
    }
    grid_bar();

    const float* epsP = isH ? eps_h : eps_c;
    const size_t muB = isH ? O_HMU  : O_CMU;
    const size_t sdB = isH ? O_HSTD : O_CSTD;
    const size_t tB  = isH ? O_HT   : O_CT;
    const __nv_bfloat16* s2H = isH ? g_nhh : g_nch;
    const __nv_bfloat16* s2L = isH ? g_nhl : g_ncl;

    const int e_b  = tid & 63;        // stage-1 pointwise (tid<256)
    const int e_nn = (tid >> 6) & 3;
    const int e2_j = tid & 7;         // stage-2 epilogue (all 512)
    const int e2_b = tid >> 3;

    // ---- loader helpers: one commit group per chunk ----
    auto issueHL = [&](const __nv_bfloat16* H, const __nv_bfloat16* L, int bf) {
        u32 d = sbA + (u32)(bf * ABUF) + (u32)(lrow * AST) + lq32;
        const char* gh = (const char*)H + lq32;
        const char* gl = (const char*)L + lq32;
        cpa16(d,              gh);
        cpa16(d + 16,         gh + 16);
        cpa16(d + 17408,      gl);
        cpa16(d + 17408 + 16, gl + 16);
        cpa_commit();
    };
    auto issue1 = [&](int s, int c, int bf) {
        if (c < 4) {
            size_t o = ((size_t)lrow * Sn + s) * 512 + c * 128;
            issueHL(g_xh + o, g_xl + o, bf);
        } else {
            size_t o = (size_t)lrow * 512 + (c - 4) * 128;
            issueHL(g_hh + o, g_hl + o, bf);
        }
    };
    auto issue2 = [&](int c, int bf) {
        size_t o = (size_t)lrow * 512 + c * 128;
        issueHL(s2H + o, s2L + o, bf);
    };

    float acc[16];
    auto compute = [&](int bf, u32 wH, u32 wL, int ktgBase) {
        u32 ab = sbA + (u32)(bf * ABUF) + aRow + aColH + (u32)(khalf * 64);
        #pragma unroll
        for (int kt = 0; kt < 2; ++kt) {
            u32 ah[4], al[4];
            ldm4(ah, ab + kt * 32);
            ldm4(al, ab + kt * 32 + 17408);
            u32 wb = (u32)((ktgBase + kt) * 512 + lane * 8);
            u32 h0a, h0b, h1a, h1b, l0a, l0b, l1a, l1b;
            lds2(h0a, h0b, wH + wb);
            lds2(h1a, h1b, wH + wb + 256);
            lds2(l0a, l0b, wL + wb);
            lds2(l1a, l1b, wL + wb + 256);
            float* A0 = acc + kt * 8;
            float* A1 = A0 + 4;
            mma16816(A0, ah, h0a, h0b);
            mma16816(A1, ah, h1a, h1b);
            mma16816(A0, ah, l0a, l0b);
            mma16816(A1, ah, l1a, l1b);
            mma16816(A0, al, h0a, h0b);
            mma16816(A1, al, h1a, h1b);
        }
    };
    auto storeDp = [&]() {
        int rlo = mt * 16 + (lane >> 2);
        int cc  = 2 * (lane & 3);
        float* dp = Dp + khalf * 1152;
        #pragma unroll
        for (int nt = 0; nt < 2; ++nt) {
            float* A = acc + nt * 4;
            float d0 = A[0] + A[8],  d1 = A[1] + A[9];
            float d2 = A[2] + A[10], d3 = A[3] + A[11];
            int c = nt * 8 + cc;
            dp[rlo * 18 + c]           = d0;
            dp[rlo * 18 + c + 1]       = d1;
            dp[(rlo + 8) * 18 + c]     = d2;
            dp[(rlo + 8) * 18 + c + 1] = d3;
        }
    };

    // prologue for s=0: stage-1 chunks 0,1 (x data)
    issue1(0, 0, 0);
    issue1(0, 1, 1);

    for (int s = 0; s < Sn; ++s) {
        // ================= stage 1 (8 chunks of K=128) =================
        #pragma unroll
        for (int i = 0; i < 16; ++i) acc[i] = 0.f;
        #pragma unroll
        for (int c = 0; c < 8; ++c) {
            if (c + 1 < 8) cpa_wait<1>(); else cpa_wait<0>();
            __syncthreads();
            compute(c % 3, sb + SO_W1H, sb + SO_W1L, c * 8 + khalf * 2);
            if (c + 2 < 8) issue1(s, c + 2, (c + 2) % 3);
        }
        storeDp();
        __syncthreads();
        if (tid < 256) {
            float gv[4];
            #pragma unroll
            for (int gg = 0; gg < 4; ++gg) {
                int c = gg * 4 + e_nn;
                float v = sB1[c];
                #pragma unroll
                for (int kp = 0; kp < 4; ++kp) v += Dp[kp * 1152 + e_b * 18 + c];
                gv[gg] = v;
            }
            int n = n0_1 + e_nn;
            float cold = __ldcg(&g_cs[e_b * 512 + n]);
            float cv = sigm(gv[1]) * cold + sigm(gv[0]) * tanhf(gv[2]);
            float hv = sigm(gv[3]) * tanhf(cv);
            __nv_bfloat16 ch = __float2bfloat16(cv);
            g_nch[e_b * 512 + n] = ch;
            g_ncl[e_b * 512 + n] = __float2bfloat16(cv - __bfloat162float(ch));
            __nv_bfloat16 hh2 = __float2bfloat16(hv);
            g_nhh[e_b * 512 + n] = hh2;
            g_nhl[e_b * 512 + n] = __float2bfloat16(hv - __bfloat162float(hh2));
        }
        grid_bar();

        // ================= stage 2 (4 chunks of K=128) =================
        #pragma unroll
        for (int i = 0; i < 16; ++i) acc[i] = 0.f;
        issue2(0, 0);
        issue2(1, 1);
        #pragma unroll
        for (int c = 0; c < 4; ++c) {
            if (c + 1 < 4) cpa_wait<1>(); else cpa_wait<0>();
            __syncthreads();
            compute(c % 3, sb + SO_W2H, sb + SO_W2L, c * 8 + khalf * 2);
            if (c + 2 < 4) issue2(c + 2, (c + 2) % 3);
        }
        storeDp();
        __syncthreads();
        {   // sample epilogue: one (b, n) per thread
            int b = e2_b;
            float pm = 0.f, ps = 0.f;
            #pragma unroll
            for (int kp = 0; kp < 4; ++kp) {
                pm += Dp[kp * 1152 + b * 18 + e2_j];
                ps += Dp[kp * 1152 + b * 18 + 8 + e2_j];
            }
            float mu = fminf(fmaxf(pm, 1e-6f), 1e6f);
            float sd = fmaxf(softplus(ps), 1e-6f);
            int n = n0_2 + e2_j;
            float e = epsP[(size_t)(s + 1) * BH + (size_t)b * 512 + n];
            float smp = fmaf(e, sd, mu);
            size_t o = (size_t)b * 262656 + (size_t)(s + 1) * 512 + n;
            out[muB + o] = mu;
            out[sdB + o] = sd;
            if (isH) {
                out[O_HID + (size_t)b * 262144 + (size_t)s * 512 + n] = smp;
                __nv_bfloat16 hh2 = __float2bfloat16(smp);
                g_hh[b * 512 + n] = hh2;
                g_hl[b * 512 + n] = __float2bfloat16(smp - __bfloat162float(hh2));
            } else {
                g_cs[b * 512 + n] = smp;
            }
            if (s == Sn - 1) out[tB + (size_t)b * 512 + n] = smp;
        }
        __syncthreads();
        // prefetch next step's x chunks across the grid barrier (bufs 0,1 free)
        if (s + 1 < Sn) {
            issue1(s + 1, 0, 0);
            issue1(s + 1, 1, 1);
        }
        grid_bar();
    }
}

extern "C" void kernel_launch(void* const* d_in, const int* in_sizes, int n_in,
                              void* d_out, int out_size) {
    (void)in_sizes; (void)n_in; (void)out_size;
    const float* x    = (const float*)d_in[0];
    const float* W_ih = (const float*)d_in[1];
    const float* W_hh = (const float*)d_in[2];
    const float* b_ih = (const float*)d_in[3];
    const float* b_hh = (const float*)d_in[4];
    const float* W_hg = (const float*)d_in[5];
    const float* W_cg = (const float*)d_in[6];
    const float* eps_h = (const float*)d_in[7];
    const float* eps_c = (const float*)d_in[8];
    float* out = (float*)d_out;

    xsplit_kernel<<<65536, 256>>>(x);

    cudaFuncSetAttribute(rglstm, cudaFuncAttributeMaxDynamicSharedMemorySize, SMEM_BYTES);
    rglstm<<<NBLK, NTHR, SMEM_BYTES>>>(W_ih, W_hh, b_ih, b_hh,
                                       W_hg, W_cg, eps_h, eps_c, out);
}